// round 5
// baseline (speedup 1.0000x reference)
#include <cuda_runtime.h>

#define B_SZ 32
#define S_LEN 2048
#define D_MODEL 1024
#define NSTATE 256
#define LN_EPS 1e-5f

#define N_CHUNK 64          // 2048 / 32
#define CHUNK_T 32          // timesteps per chunk
#define N_WORKER_BLK 116
#define N_WORKER_WARP (N_WORKER_BLK * 8)
#define GRID_TOTAL (B_SZ + N_WORKER_BLK)

__device__ float g_u[B_SZ * S_LEN];
__device__ float g_s[B_SZ * S_LEN];
__device__ int   g_ucnt[N_CHUNK];   // rows completed per t-chunk (1024 rows each)
__device__ int   g_swm[B_SZ];       // per-batch s watermark (t values flushed)

__device__ __forceinline__ float warp_sum(float v) {
    #pragma unroll
    for (int o = 16; o; o >>= 1) v += __shfl_xor_sync(0xffffffffu, v, o);
    return v;
}

__global__ void init_kernel() {
    int t = threadIdx.x;
    if (t < N_CHUNK) g_ucnt[t] = 0;
    if (t < B_SZ) g_swm[t] = 0;
}

__global__ void __launch_bounds__(256, 1) fused_kernel(
    const float* __restrict__ x,
    const float* __restrict__ llr,
    const float* __restrict__ logb,
    const float* __restrict__ cvec,
    const float* __restrict__ logd,
    const float* __restrict__ logstep,
    const float* __restrict__ alpha,
    const float* __restrict__ lngamma,
    const float* __restrict__ lnbeta,
    float* __restrict__ out)
{
    __shared__ float su[S_LEN + 32];
    __shared__ float ss[S_LEN];
    __shared__ int s_uready;   // chunks of u staged into su
    __shared__ int s_scant;    // timesteps of ss completed by scan warp

    const int bid = blockIdx.x;
    const int wid = threadIdx.x >> 5;
    const int lane = threadIdx.x & 31;

    if (bid < B_SZ) {
        // ───────────────────────── scanner block (batch b = bid) ─────────────────────────
        const int b = bid;
        if (threadIdx.x == 0) { s_uready = 0; s_scant = 0; }
        __syncwarp();  // warp-local; cross-warp init visibility handled by polling from 0

        if (wid == 1) {
            // u stager: poll chunk counters, copy u[b, chunk] into su
            // NOTE: s_uready starts whenever we first write it; consumers poll >= value,
            // and we only ever publish after staging, so initial garbage is avoided by
            // having thread 0 of warp1 also write 0 first.
            if (lane == 0) atomicExch(&s_uready, 0);
            __syncwarp();
            for (int c = 0; c < N_CHUNK; c++) {
                while (*(volatile int*)&g_ucnt[c] < B_SZ * CHUNK_T) __nanosleep(100);
                __threadfence();
                su[c * CHUNK_T + lane] = g_u[(size_t)b * S_LEN + c * CHUNK_T + lane];
                __threadfence_block();
                __syncwarp();
                if (lane == 0) *(volatile int*)&s_uready = c + 1;
            }
            return;
        }
        if (wid == 2) {
            // s flusher: wait for scan warp to finish each chunk, flush to gmem, publish watermark
            for (int c = 0; c < N_CHUNK; c++) {
                while (*(volatile int*)&s_scant < (c + 1) * CHUNK_T) __nanosleep(100);
                __threadfence_block();
                g_s[(size_t)b * S_LEN + c * CHUNK_T + lane] = ss[c * CHUNK_T + lane];
                __threadfence();
                __syncwarp();
                if (lane == 0) *(volatile int*)&g_swm[b] = (c + 1) * CHUNK_T;
            }
            return;
        }
        if (wid != 0) return;

        // ── scan warp ──
        if (lane == 0) atomicExch(&s_scant, 0);

        const float step = expf(logstep[0]);
        float ag[8], ab_[8], bd[8], gc[8], z[8];
        float pgc = 0.f, pbc = 0.f;
        #pragma unroll
        for (int j = 0; j < 8; j++) {
            int i = lane + 32 * j;
            float lam = -expf(llr[i]);
            float a   = (2.0f + step * lam) / (2.0f - step * lam);
            float bb  = expf(logb[i]);
            bd[j] = step * (1.0f + a) * bb * 0.5f;
            float g  = lngamma[i];
            float be = lnbeta[i];
            float cc = cvec[i];
            ag[j]  = a * g;
            ab_[j] = a * be;
            gc[j]  = g * cc;
            pgc += g * cc;
            pbc += be * cc;
        }
        const float Sgc = warp_sum(pgc);
        const float Sbc = warp_sum(pbc);

        // wait for first u chunk
        while (*(volatile int*)&s_uready < 1) __nanosleep(60);
        __syncwarp();

        {
            float u0 = su[0];
            #pragma unroll
            for (int j = 0; j < 8; j++) z[j] = bd[j] * u0;
        }

        const float invn = 1.0f / (float)NSTATE;
        for (int t = 0; t < S_LEN; t++) {
            float q[8], m[8];
            #pragma unroll
            for (int j = 0; j < 8; j++) { q[j] = z[j] * z[j]; m[j] = z[j] * gc[j]; }
            float p1 = ((z[0] + z[1]) + (z[2] + z[3])) + ((z[4] + z[5]) + (z[6] + z[7]));
            float p2 = ((q[0] + q[1]) + (q[2] + q[3])) + ((q[4] + q[5]) + (q[6] + q[7]));
            float p3 = ((m[0] + m[1]) + (m[2] + m[3])) + ((m[4] + m[5]) + (m[6] + m[7]));

            #pragma unroll
            for (int o = 16; o; o >>= 1) {
                p1 += __shfl_xor_sync(0xffffffffu, p1, o);
                p2 += __shfl_xor_sync(0xffffffffu, p2, o);
                p3 += __shfl_xor_sync(0xffffffffu, p3, o);
            }

            float mu  = p1 * invn;
            float var = fmaf(p2, invn, -mu * mu);
            float rs  = rsqrtf(var + LN_EPS);

            if (lane == 0) ss[t] = fmaf(rs, fmaf(-mu, Sgc, p3), Sbc);

            if (t + 1 < S_LEN) {
                // make sure next chunk of u is staged (checked at chunk boundary)
                if (((t + 1) & (CHUNK_T - 1)) == 0) {
                    int need = ((t + 1) >> 5) + 1;
                    while (*(volatile int*)&s_uready < need) __nanosleep(60);
                }
                float un = su[t + 1];
                #pragma unroll
                for (int j = 0; j < 8; j++) {
                    float cst = fmaf(bd[j], un, ab_[j]);
                    z[j] = fmaf((z[j] - mu) * rs, ag[j], cst);
                }
            }
            if ((t & (CHUNK_T - 1)) == (CHUNK_T - 1)) {
                __threadfence_block();
                __syncwarp();
                if (lane == 0) *(volatile int*)&s_scant = t + 1;
            }
        }
        return;
    }

    // ───────────────────────── worker block ─────────────────────────
    const int wg = (bid - B_SZ) * 8 + wid;   // 0 .. 927

    // Phase 1: mean, rows in t-major order  (r = t*32 + b)
    for (int r = wg; r < B_SZ * S_LEN; r += N_WORKER_WARP) {
        int t = r >> 5;
        int b = r & 31;
        const float4* xp = (const float4*)(x + ((size_t)b * S_LEN + t) * D_MODEL);
        float s = 0.f;
        #pragma unroll
        for (int k = 0; k < 8; k++) {
            float4 v = xp[lane + 32 * k];
            s += (v.x + v.y) + (v.z + v.w);
        }
        s = warp_sum(s);
        if (lane == 0) {
            g_u[(size_t)b * S_LEN + t] = s * (1.0f / (float)D_MODEL);
            __threadfence();
            atomicAdd(&g_ucnt[t >> 5], 1);
        }
    }

    // Phase 2: out, rows in t-major order, gated on per-batch watermark
    float a_sig = 1.0f / (1.0f + expf(-alpha[0]));
    float dd = expf(logd[0]);
    float c1 = a_sig + (1.0f - a_sig) * dd;
    float c2 = 1.0f - a_sig;

    for (int r = wg; r < B_SZ * S_LEN; r += N_WORKER_WARP) {
        int t = r >> 5;
        int b = r & 31;
        while (*(volatile int*)&g_swm[b] <= t) __nanosleep(150);
        __threadfence();
        float c2s = c2 * g_s[(size_t)b * S_LEN + t];

        const float4* xp = (const float4*)(x + ((size_t)b * S_LEN + t) * D_MODEL);
        float4* op = (float4*)(out + ((size_t)b * S_LEN + t) * D_MODEL);
        #pragma unroll
        for (int k = 0; k < 8; k++) {
            float4 v = xp[lane + 32 * k];
            v.x = fmaf(c1, v.x, c2s);
            v.y = fmaf(c1, v.y, c2s);
            v.z = fmaf(c1, v.z, c2s);
            v.w = fmaf(c1, v.w, c2s);
            op[lane + 32 * k] = v;
        }
    }
}

extern "C" void kernel_launch(void* const* d_in, const int* in_sizes, int n_in,
                              void* d_out, int out_size) {
    const float* x        = (const float*)d_in[0];
    const float* llr      = (const float*)d_in[1];
    const float* logb     = (const float*)d_in[2];
    const float* cvec     = (const float*)d_in[3];
    const float* logd     = (const float*)d_in[4];
    const float* logstep  = (const float*)d_in[5];
    const float* alpha    = (const float*)d_in[6];
    const float* lngamma  = (const float*)d_in[7];
    const float* lnbeta   = (const float*)d_in[8];
    float* out = (float*)d_out;

    init_kernel<<<1, 256>>>();
    fused_kernel<<<GRID_TOTAL, 256>>>(x, llr, logb, cvec, logd, logstep,
                                      alpha, lngamma, lnbeta, out);
}

// round 6
// speedup vs baseline: 1.3968x; 1.3968x over previous
#include <cuda_runtime.h>

#define B_SZ 32
#define S_LEN 2048
#define D_MODEL 1024
#define NSTATE 256
#define LN_EPS 1e-5f

__device__ float g_u[B_SZ * S_LEN];
__device__ float g_s[B_SZ * S_LEN];

__device__ __forceinline__ float warp_sum(float v) {
    #pragma unroll
    for (int o = 16; o; o >>= 1) v += __shfl_xor_sync(0xffffffffu, v, o);
    return v;
}

// Kernel 1: u[b,s] = mean_k x[b,s,k].  One warp per row of 1024.  (at DRAM roofline)
__global__ void mean_kernel(const float* __restrict__ x) {
    int gwarp = (blockIdx.x * blockDim.x + threadIdx.x) >> 5;
    int lane  = threadIdx.x & 31;
    const float4* xp = (const float4*)(x + (size_t)gwarp * D_MODEL);
    float s = 0.f;
    #pragma unroll
    for (int k = 0; k < 8; k++) {
        float4 v = xp[lane + 32 * k];
        s += (v.x + v.y) + (v.z + v.w);
    }
    s = warp_sum(s);
    if (lane == 0) g_u[gwarp] = s * (1.0f / (float)D_MODEL);
}

// Kernel 2: sequential scan, one warp per batch, 8 states/lane.
// 2-step analytic lookahead: one 9-channel butterfly per 2 timesteps.
//   z_{t+1}[i] = rs_t*(z_t[i]-mu_t)*A[i] + AB[i] + BD[i]*u_{t+1}
//   s_t        = rs_t*(S3_t - mu_t*Sgc) + Sbc ,  S3 = sum(gc*z)
// Step t computed from direct reductions of z_t; step t+1 scalars computed
// analytically from moments of z_t; z advanced two steps exactly.
__global__ void __launch_bounds__(32, 1) scan_kernel(
                            const float* __restrict__ llr,
                            const float* __restrict__ logb,
                            const float* __restrict__ cvec,
                            const float* __restrict__ logstep,
                            const float* __restrict__ lngamma,
                            const float* __restrict__ lnbeta) {
    __shared__ float su[S_LEN];
    __shared__ float ss[S_LEN];
    const int b = blockIdx.x;
    const int lane = threadIdx.x;

    // Stage this batch's u row into SMEM.
    {
        const float4* up = (const float4*)(g_u + (size_t)b * S_LEN);
        float4* sp = (float4*)su;
        #pragma unroll
        for (int k = 0; k < 16; k++) sp[lane + 32 * k] = up[lane + 32 * k];
    }

    const float step = expf(logstep[0]);
    float A[8], AB[8], BD[8], GC[8], QGC[8], QAB[8], QBD[8], z[8];
    // per-lane partial scalars for the 13 constant reductions
    float pgc=0.f, pbc=0.f, pca=0.f, pca2=0.f, pgca=0.f, pcab=0.f, pcbd=0.f,
          pgcab=0.f, pgcbd=0.f, pcaab=0.f, pcabd=0.f, pab2=0.f, pabbd=0.f, pbd2=0.f;
    #pragma unroll
    for (int j = 0; j < 8; j++) {
        int i = lane + 32 * j;
        float lam = -expf(llr[i]);
        float ad  = (2.0f + step * lam) / (2.0f - step * lam);
        float bb  = expf(logb[i]);
        float bd  = step * (1.0f + ad) * bb * 0.5f;
        float g   = lngamma[i];
        float be  = lnbeta[i];
        float cc  = cvec[i];
        float a   = ad * g;     // recurrence multiplier
        float ab  = ad * be;    // recurrence offset (beta part)
        float gc  = g * cc;
        A[j]=a; AB[j]=ab; BD[j]=bd; GC[j]=gc;
        QGC[j]=gc*a; QAB[j]=a*ab; QBD[j]=a*bd;
        pgc  += gc;        pbc  += be*cc;
        pca  += a;         pca2 += a*a;      pgca += gc*a;
        pcab += ab;        pcbd += bd;
        pgcab+= gc*ab;     pgcbd+= gc*bd;
        pcaab+= a*ab;      pcabd+= a*bd;
        pab2 += ab*ab;     pabbd+= ab*bd;    pbd2 += bd*bd;
    }
    const float Sgc   = warp_sum(pgc);
    const float Sbc   = warp_sum(pbc);
    const float Ca    = warp_sum(pca);
    const float Ca2   = warp_sum(pca2);
    const float Cgca  = warp_sum(pgca);
    const float Cab   = warp_sum(pcab);
    const float Cbd   = warp_sum(pcbd);
    const float Cgcab = warp_sum(pgcab);
    const float Cgcbd = warp_sum(pgcbd);
    const float Caab  = warp_sum(pcaab);
    const float Cabd  = warp_sum(pcabd);
    const float Cab2  = warp_sum(pab2);
    const float Cabbd = warp_sum(pabbd);
    const float Cbd2  = warp_sum(pbd2);

    __syncwarp();
    {
        float u0 = su[0];
        #pragma unroll
        for (int j = 0; j < 8; j++) z[j] = BD[j] * u0;   // h0 = 0
    }

    const float invn = 1.0f / (float)NSTATE;
    for (int t = 0; t < S_LEN; t += 2) {
        // ── 9-channel lane-local partial sums over z_t ──
        float p0=0.f,p1=0.f,p2=0.f,p3=0.f,p4=0.f,p5=0.f,p6=0.f,p7=0.f,p8=0.f;
        #pragma unroll
        for (int j = 0; j < 8; j++) {
            float zz = z[j];
            float az = A[j] * zz;
            p0 += zz;            // S1  = sum z
            p1 += zz * zz;       // S2  = sum z^2
            p2 += GC[j] * zz;    // S3  = sum gc z
            p3 += az;            // A1  = sum A z
            p4 += A[j] * az;     // A2a = sum A^2 z
            p5 += az * az;       // A2  = sum A^2 z^2
            p6 += QGC[j] * zz;   // G1  = sum gc A z
            p7 += QAB[j] * zz;   // Aab = sum A*AB z
            p8 += QBD[j] * zz;   // Abd = sum A*BD z
        }

        // ── one butterfly for all 9 channels ──
        #pragma unroll
        for (int o = 16; o; o >>= 1) {
            p0 += __shfl_xor_sync(0xffffffffu, p0, o);
            p1 += __shfl_xor_sync(0xffffffffu, p1, o);
            p2 += __shfl_xor_sync(0xffffffffu, p2, o);
            p3 += __shfl_xor_sync(0xffffffffu, p3, o);
            p4 += __shfl_xor_sync(0xffffffffu, p4, o);
            p5 += __shfl_xor_sync(0xffffffffu, p5, o);
            p6 += __shfl_xor_sync(0xffffffffu, p6, o);
            p7 += __shfl_xor_sync(0xffffffffu, p7, o);
            p8 += __shfl_xor_sync(0xffffffffu, p8, o);
        }

        // ── step t scalars (direct) ──
        float mu  = p0 * invn;
        float var = fmaf(p1, invn, -mu * mu);
        float rs  = rsqrtf(var + LN_EPS);
        float u1  = su[t + 1];

        // ── step t+1 sums (analytic) ──
        float S1n = fmaf(rs, fmaf(-mu, Ca, p3), fmaf(Cbd, u1, Cab));
        float S3n = fmaf(rs, fmaf(-mu, Cgca, p6), fmaf(Cgcbd, u1, Cgcab));
        float T2  = fmaf(mu * mu, Ca2, fmaf(-2.0f * mu, p4, p5));
        float T1  = fmaf(u1, p8, p7) - mu * fmaf(u1, Cabd, Caab);
        float T0  = fmaf(u1 * u1, Cbd2, fmaf(2.0f * u1, Cabbd, Cab2));
        float S2n = fmaf(rs * rs, T2, fmaf(2.0f * rs, T1, T0));

        float mun  = S1n * invn;
        float varn = fmaf(S2n, invn, -mun * mun);
        float rsn  = rsqrtf(varn + LN_EPS);

        if (lane == 0) {
            ss[t]     = fmaf(rs,  fmaf(-mu,  Sgc, p2),  Sbc);
            ss[t + 1] = fmaf(rsn, fmaf(-mun, Sgc, S3n), Sbc);
        }

        // ── advance z two steps (exact lane-local recurrence) ──
        float u2 = (t + 2 < S_LEN) ? su[t + 2] : 0.0f;
        #pragma unroll
        for (int j = 0; j < 8; j++) {
            float cst1 = fmaf(BD[j], u1, AB[j]);
            float z1   = fmaf((z[j] - mu) * rs, A[j], cst1);
            float cst2 = fmaf(BD[j], u2, AB[j]);
            z[j]       = fmaf((z1 - mun) * rsn, A[j], cst2);
        }
    }

    __syncwarp();
    {
        float4* gp = (float4*)(g_s + (size_t)b * S_LEN);
        const float4* sp = (const float4*)ss;
        #pragma unroll
        for (int k = 0; k < 16; k++) gp[lane + 32 * k] = sp[lane + 32 * k];
    }
}

// Kernel 3: out[b,s,:] = c1 * x[b,s,:] + c2 * s[b,s]   (at DRAM roofline)
__global__ void out_kernel(const float* __restrict__ x,
                           const float* __restrict__ alpha,
                           const float* __restrict__ logd,
                           float* __restrict__ out) {
    const int row = blockIdx.x;
    const int tid = threadIdx.x;
    float a_sig = 1.0f / (1.0f + expf(-alpha[0]));
    float dd = expf(logd[0]);
    float c1 = a_sig + (1.0f - a_sig) * dd;
    float c2s = (1.0f - a_sig) * g_s[row];

    const float4* xp = (const float4*)(x + (size_t)row * D_MODEL);
    float4* op = (float4*)(out + (size_t)row * D_MODEL);
    float4 v = xp[tid];
    v.x = fmaf(c1, v.x, c2s);
    v.y = fmaf(c1, v.y, c2s);
    v.z = fmaf(c1, v.z, c2s);
    v.w = fmaf(c1, v.w, c2s);
    op[tid] = v;
}

extern "C" void kernel_launch(void* const* d_in, const int* in_sizes, int n_in,
                              void* d_out, int out_size) {
    const float* x        = (const float*)d_in[0];
    const float* llr      = (const float*)d_in[1];
    const float* logb     = (const float*)d_in[2];
    const float* cvec     = (const float*)d_in[3];
    const float* logd     = (const float*)d_in[4];
    const float* logstep  = (const float*)d_in[5];
    const float* alpha    = (const float*)d_in[6];
    const float* lngamma  = (const float*)d_in[7];
    const float* lnbeta   = (const float*)d_in[8];
    float* out = (float*)d_out;

    mean_kernel<<<(B_SZ * S_LEN) / 8, 256>>>(x);
    scan_kernel<<<B_SZ, 32>>>(llr, logb, cvec, logstep, lngamma, lnbeta);
    out_kernel<<<B_SZ * S_LEN, 256>>>(x, alpha, logd, out);
}